// round 6
// baseline (speedup 1.0000x reference)
#include <cuda_runtime.h>
#include <math.h>

#define CC    128
#define GENES 4096

// ---- main (len<=32) kernel geometry ----
#define SR32  132                 // row stride (floats)
#define SKT32 33                  // K^T stride
#define B32   (32 * SR32)         // 4224 floats
#define KT32  (128 * SKT32)       // 4224 floats
#define SM32_FLOATS (3 * B32 + KT32 + 256)
#define SM32_BYTES  (SM32_FLOATS * 4)      // ~68.6 KB -> 3 CTAs/SM

// ---- long (len>32) kernel geometry ----
#define SR64  136
#define SKT64 69
#define B64   (64 * SR64)
#define KT64  (128 * SKT64)
#define SM64_FLOATS (3 * B64 + KT64 + 256)
#define SM64_BYTES  (SM64_FLOATS * 4)

__device__ int g_starts[GENES + 1];
__device__ int g_longcount;
__device__ int g_longlist[GENES];

__device__ __forceinline__ float warp_sum(float v) {
#pragma unroll
    for (int o = 16; o; o >>= 1) v += __shfl_xor_sync(0xffffffffu, v, o);
    return v;
}
__device__ __forceinline__ float warp_max(float v) {
#pragma unroll
    for (int o = 16; o; o >>= 1) v = fmaxf(v, __shfl_xor_sync(0xffffffffu, v, o));
    return v;
}

// ============================================================================
// bounds kernel: mark segment starts (gene_idx sorted, every gene nonempty)
// ============================================================================
__global__ void seg_bounds_kernel(const int* __restrict__ gene_idx, int E)
{
    int e = blockIdx.x * 256 + threadIdx.x;
    if (e == 0) { g_starts[GENES] = E; g_longcount = 0; }
    if (e < E) {
        int gi = gene_idx[e];
        if (e == 0 || gene_idx[e - 1] != gi) g_starts[gi] = e;
    }
}

// ============================================================================
// mm32: X[rows<=32,128] @ W + b -> Y.  8 warps = 2 row-groups x 4 col-quarters.
// Each warp loads only a QUARTER of W (32 cols, 1 col per lane -> 16KB/warp).
// X loads are warp-broadcast LDS (conflict-free). acc[16] registers.
// TRANS: write Y transposed with stride SKT32. RELU: fused relu.
// ============================================================================
template <bool TRANS, bool RELU>
__device__ void mm32(const float* X, const float* __restrict__ W,
                     const float* __restrict__ bias, float* Y,
                     int rows, int w, int lane)
{
    int rg = w >> 2;                    // 0..1, rows rg, rg+2, rg+4, ...
    int cq = w & 3;                     // col quarter
    int c0 = cq * 32 + lane;            // one output column per lane
    int nr = (rows > rg) ? (((rows - 1 - rg) >> 1) + 1) : 0;   // <= 16
    if (nr == 0) return;
    float acc[16];
#pragma unroll
    for (int i = 0; i < 16; i++) acc[i] = 0.f;

#pragma unroll 2
    for (int kk = 0; kk < CC; kk += 4) {
        float w0 = W[(kk + 0) * CC + c0];
        float w1 = W[(kk + 1) * CC + c0];
        float w2 = W[(kk + 2) * CC + c0];
        float w3 = W[(kk + 3) * CC + c0];
#pragma unroll
        for (int i = 0; i < 16; i++) {
            if (i < nr) {   // nr is warp-uniform
                float4 xv = *(const float4*)(X + (rg + 2 * i) * SR32 + kk);
                acc[i] = fmaf(xv.x, w0, acc[i]);
                acc[i] = fmaf(xv.y, w1, acc[i]);
                acc[i] = fmaf(xv.z, w2, acc[i]);
                acc[i] = fmaf(xv.w, w3, acc[i]);
            }
        }
    }
    float bv = bias[c0];
#pragma unroll
    for (int i = 0; i < 16; i++) {
        if (i < nr) {
            int r = rg + 2 * i;
            float o = acc[i] + bv;
            if (RELU) o = fmaxf(o, 0.f);
            if (!TRANS) {
                Y[r * SR32 + c0] = o;          // 32 consecutive -> conflict-free
            } else {
                Y[c0 * SKT32 + r] = o;          // stride 33 -> distinct banks
            }
        }
    }
}

// ============================================================================
// mm64row: original row-split matmul for the long (64-row) kernel
// ============================================================================
template <bool TRANS, bool RELU>
__device__ void mm64row(const float* X, const float* __restrict__ W,
                        const float* __restrict__ bias, float* Y,
                        int rows, int w, int lane)
{
    int nr = (rows > w) ? (((rows - 1 - w) >> 3) + 1) : 0;
    if (nr == 0) return;
    int c0 = lane * 4;
    float acc[8][4];
#pragma unroll
    for (int i = 0; i < 8; i++) { acc[i][0]=0.f; acc[i][1]=0.f; acc[i][2]=0.f; acc[i][3]=0.f; }

#pragma unroll 2
    for (int kk = 0; kk < CC; kk += 4) {
        float4 w0 = *(const float4*)(W + (kk + 0) * CC + c0);
        float4 w1 = *(const float4*)(W + (kk + 1) * CC + c0);
        float4 w2 = *(const float4*)(W + (kk + 2) * CC + c0);
        float4 w3 = *(const float4*)(W + (kk + 3) * CC + c0);
#pragma unroll
        for (int i = 0; i < 8; i++) {
            if (i < nr) {
                float4 xv = *(const float4*)(X + (w + 8 * i) * SR64 + kk);
                acc[i][0]=fmaf(xv.x,w0.x,acc[i][0]); acc[i][1]=fmaf(xv.x,w0.y,acc[i][1]);
                acc[i][2]=fmaf(xv.x,w0.z,acc[i][2]); acc[i][3]=fmaf(xv.x,w0.w,acc[i][3]);
                acc[i][0]=fmaf(xv.y,w1.x,acc[i][0]); acc[i][1]=fmaf(xv.y,w1.y,acc[i][1]);
                acc[i][2]=fmaf(xv.y,w1.z,acc[i][2]); acc[i][3]=fmaf(xv.y,w1.w,acc[i][3]);
                acc[i][0]=fmaf(xv.z,w2.x,acc[i][0]); acc[i][1]=fmaf(xv.z,w2.y,acc[i][1]);
                acc[i][2]=fmaf(xv.z,w2.z,acc[i][2]); acc[i][3]=fmaf(xv.z,w2.w,acc[i][3]);
                acc[i][0]=fmaf(xv.w,w3.x,acc[i][0]); acc[i][1]=fmaf(xv.w,w3.y,acc[i][1]);
                acc[i][2]=fmaf(xv.w,w3.z,acc[i][2]); acc[i][3]=fmaf(xv.w,w3.w,acc[i][3]);
            }
        }
    }
    float4 bv = *(const float4*)(bias + c0);
#pragma unroll
    for (int i = 0; i < 8; i++) {
        if (i < nr) {
            int r = w + 8 * i;
            float o0=acc[i][0]+bv.x, o1=acc[i][1]+bv.y, o2=acc[i][2]+bv.z, o3=acc[i][3]+bv.w;
            if (RELU) { o0=fmaxf(o0,0.f); o1=fmaxf(o1,0.f); o2=fmaxf(o2,0.f); o3=fmaxf(o3,0.f); }
            if (!TRANS) {
                *(float4*)(Y + r * SR64 + c0) = make_float4(o0, o1, o2, o3);
            } else {
                Y[(c0+0)*SKT64 + r]=o0; Y[(c0+1)*SKT64 + r]=o1;
                Y[(c0+2)*SKT64 + r]=o2; Y[(c0+3)*SKT64 + r]=o3;
            }
        }
    }
}

// ============================================================================
// mm1 split over k (2 halves across 256 threads) + finalize
// ============================================================================
__device__ void mm1_part(const float* __restrict__ X, const float* __restrict__ W,
                         float* scratch, int tid)
{
    int col = tid & 127;
    int h   = tid >> 7;                 // 0/1
    const float* Wp = W + (h * 64) * CC + col;
    const float* Xp = X + h * 64;
    float acc = 0.f;
#pragma unroll 8
    for (int k = 0; k < 64; k++) acc = fmaf(Xp[k], Wp[k * CC], acc);
    scratch[tid] = acc;
}
template <bool RELU>
__device__ void mm1_fin(const float* scratch, const float* __restrict__ bias,
                        float* Y, int tid)
{
    if (tid < CC) {
        float v = scratch[tid] + scratch[tid + 128] + bias[tid];
        if (RELU) v = fmaxf(v, 0.f);
        Y[tid] = v;
    }
}

// ============================================================================
// attention (kv <= 32): one warp per (query row, head), lane = kv index
// ============================================================================
template <int SROW, int SKTV>
__device__ void attn32(float* QO, const float* Kt, const float* V,
                       int Lq, int len, int kvr, int w, int lane)
{
    const float scale = 0.17677669529663687f;   // 1/sqrt(32)
    int ntask = Lq * 4;
    for (int t = w; t < ntask; t += 8) {
        int r = t >> 2, base = (t & 3) * 32;
        float s = 0.f;
#pragma unroll
        for (int d = 0; d < 32; d++)
            s = fmaf(QO[r * SROW + base + d], Kt[(base + d) * SKTV + lane], s);
        s = (lane < len) ? s * scale : -1e30f;
        float m = warp_max(s);
        float p = __expf(s - m);
        float inv = 1.f / warp_sum(p);
        float a = p * inv;
        float acc = 0.f;
        for (int k = 0; k < kvr; k++)
            acc = fmaf(__shfl_sync(0xffffffffu, a, k), V[k * SROW + base + lane], acc);
        QO[r * SROW + base + lane] = acc;
    }
}

// attention (kv <= 64) for the long kernel
__device__ void attn64(float* QO, const float* Kt, const float* V,
                       int Lq, int len, int kvr, int w, int lane)
{
    const float scale = 0.17677669529663687f;
    int ntask = Lq * 4;
    for (int t = w; t < ntask; t += 8) {
        int r = t >> 2, base = (t & 3) * 32;
        float s0 = 0.f, s1 = 0.f;
#pragma unroll
        for (int d = 0; d < 32; d++) {
            float qd = QO[r * SR64 + base + d];
            s0 = fmaf(qd, Kt[(base + d) * SKT64 + lane], s0);
            s1 = fmaf(qd, Kt[(base + d) * SKT64 + lane + 32], s1);
        }
        s0 = (lane < len)      ? s0 * scale : -1e30f;
        s1 = (lane + 32 < len) ? s1 * scale : -1e30f;
        float m = warp_max(fmaxf(s0, s1));
        float p0 = __expf(s0 - m), p1 = __expf(s1 - m);
        float inv = 1.f / warp_sum(p0 + p1);
        float a0 = p0 * inv, a1 = p1 * inv;
        float acc = 0.f;
        int k0 = kvr < 32 ? kvr : 32;
        for (int k = 0; k < k0; k++)
            acc = fmaf(__shfl_sync(0xffffffffu, a0, k), V[k * SR64 + base + lane], acc);
        for (int k = 32; k < kvr; k++)
            acc = fmaf(__shfl_sync(0xffffffffu, a1, k - 32), V[k * SR64 + base + lane], acc);
        QO[r * SR64 + base + lane] = acc;
    }
}

// ============================================================================
// LN(residual + masked A) row-wise over 128
// ============================================================================
template <int SROW>
__device__ void lnres(const float* A, const float* Res, float* Out,
                      int rows, int qmasklen,
                      const float* __restrict__ g, const float* __restrict__ b,
                      int w, int lane)
{
    for (int r = w; r < rows; r += 8) {
        float4 a = (r < qmasklen) ? *(const float4*)(A + r * SROW + lane * 4)
                                  : make_float4(0.f, 0.f, 0.f, 0.f);
        float4 s = *(const float4*)(Res + r * SROW + lane * 4);
        float t0 = a.x + s.x, t1 = a.y + s.y, t2 = a.z + s.z, t3 = a.w + s.w;
        float sum = warp_sum(t0 + t1 + t2 + t3);
        float sq  = warp_sum(t0*t0 + t1*t1 + t2*t2 + t3*t3);
        float mean = sum * (1.f / 128.f);
        float var  = sq * (1.f / 128.f) - mean * mean;
        float rstd = rsqrtf(var + 1e-5f);
        float4 gv = *(const float4*)(g + lane * 4);
        float4 bv = *(const float4*)(b + lane * 4);
        float4 o;
        o.x = (t0 - mean) * rstd * gv.x + bv.x;
        o.y = (t1 - mean) * rstd * gv.y + bv.y;
        o.z = (t2 - mean) * rstd * gv.z + bv.z;
        o.w = (t3 - mean) * rstd * gv.w + bv.w;
        *(float4*)(Out + r * SROW + lane * 4) = o;
    }
}

// ============================================================================
// MAIN kernel: genes with len <= 32 (3 CTAs/SM)
// ============================================================================
__global__ __launch_bounds__(256, 3)
void gene_main32(const float* __restrict__ rf,
                 const float* __restrict__ Wq, const float* __restrict__ Wk,
                 const float* __restrict__ Wv, const float* __restrict__ Wo,
                 const float* __restrict__ bq, const float* __restrict__ bk,
                 const float* __restrict__ bv, const float* __restrict__ bo,
                 const float* __restrict__ Wlin, const float* __restrict__ blin,
                 const float* __restrict__ g1, const float* __restrict__ b1,
                 const float* __restrict__ g2, const float* __restrict__ b2,
                 const float* __restrict__ seed,
                 const int* __restrict__ rxn_idx,
                 float* __restrict__ out)
{
    extern __shared__ float sm[];
    float* Sst = sm;                    // state        [32][SR32]
    float* SA  = sm + B32;              // Q / attn-O   [32][SR32]
    float* SB  = SA + B32;              // K^T [128][SKT32] OR normal [32][SR32]
    float* SC  = SB + KT32;             // V / FF       [32][SR32]
    float* SCR = SC + B32;              // mm1 scratch  [256]

    int g    = blockIdx.x;
    int tid  = threadIdx.x;
    int w    = tid >> 5;
    int lane = tid & 31;

    int start = g_starts[g];
    int len   = g_starts[g + 1] - start;
    if (len > 32) {                     // defer to long kernel
        if (tid == 0) { int p = atomicAdd(&g_longcount, 1); g_longlist[p] = g; }
        return;
    }
    int lenr = (len + 7) & ~7;          // 8..32

    // gather
    for (int r = w; r < lenr; r += 8) {
        if (r < len) {
            int rx = rxn_idx[start + r];
            ((float4*)(Sst + r * SR32))[lane] = ((const float4*)(rf + (size_t)rx * CC))[lane];
        } else {
            ((float4*)(Sst + r * SR32))[lane] = make_float4(0.f, 0.f, 0.f, 0.f);
        }
    }
    __syncthreads();

    // encoder SABs
    for (int blk = 0; blk < 2; blk++) {
        const float* wq = Wq + blk * CC * CC;  const float* wk = Wk + blk * CC * CC;
        const float* wv = Wv + blk * CC * CC;  const float* wo = Wo + blk * CC * CC;
        const float* wl = Wlin + blk * CC * CC;
        mm32<false, false>(Sst, wq, bq + blk * CC, SA, lenr, w, lane);
        mm32<true,  false>(Sst, wk, bk + blk * CC, SB, lenr, w, lane);
        mm32<false, false>(Sst, wv, bv + blk * CC, SC, lenr, w, lane);
        __syncthreads();
        attn32<SR32, SKT32>(SA, SB, SC, lenr, len, lenr, w, lane);
        __syncthreads();
        mm32<false, false>(SA, wo, bo + blk * CC, SB, lenr, w, lane);
        __syncthreads();
        lnres<SR32>(SB, Sst, Sst, lenr, len, g1 + blk * CC, b1 + blk * CC, w, lane);
        __syncthreads();
        mm32<false, true>(Sst, wl, blin + blk * CC, SC, lenr, w, lane);
        __syncthreads();
        lnres<SR32>(SC, Sst, Sst, lenr, lenr, g2 + blk * CC, b2 + blk * CC, w, lane);
        __syncthreads();
    }

    // PMA (block 2)
    {
        const int blk = 2;
        mm1_part(seed, Wq + blk * CC * CC, SCR, tid);
        mm32<true,  false>(Sst, Wk + blk * CC * CC, bk + blk * CC, SB, lenr, w, lane);
        mm32<false, false>(Sst, Wv + blk * CC * CC, bv + blk * CC, SC, lenr, w, lane);
        __syncthreads();
        mm1_fin<false>(SCR, bq + blk * CC, SA, tid);    // Q row0
        __syncthreads();
        attn32<SR32, SKT32>(SA, SB, SC, 1, len, lenr, w, lane);
        __syncthreads();
        mm1_part(SA, Wo + blk * CC * CC, SCR, tid);
        __syncthreads();
        mm1_fin<false>(SCR, bo + blk * CC, SB, tid);
        __syncthreads();
        lnres<SR32>(SB, seed, Sst, 1, 1, g1 + blk * CC, b1 + blk * CC, w, lane);
        __syncthreads();
        mm1_part(Sst, Wlin + blk * CC * CC, SCR, tid);
        __syncthreads();
        mm1_fin<true>(SCR, blin + blk * CC, SC, tid);
        __syncthreads();
        lnres<SR32>(SC, Sst, Sst, 1, 1, g2 + blk * CC, b2 + blk * CC, w, lane);
        __syncthreads();
    }

    // decoder SAB (block 3): Lq=Lk=1 -> attn = V
    {
        const int blk = 3;
        mm1_part(Sst, Wv + blk * CC * CC, SCR, tid);
        __syncthreads();
        mm1_fin<false>(SCR, bv + blk * CC, SA, tid);
        __syncthreads();
        mm1_part(SA, Wo + blk * CC * CC, SCR, tid);
        __syncthreads();
        mm1_fin<false>(SCR, bo + blk * CC, SB, tid);
        __syncthreads();
        lnres<SR32>(SB, Sst, Sst, 1, 1, g1 + blk * CC, b1 + blk * CC, w, lane);
        __syncthreads();
        mm1_part(Sst, Wlin + blk * CC * CC, SCR, tid);
        __syncthreads();
        mm1_fin<true>(SCR, blin + blk * CC, SC, tid);
        __syncthreads();
        lnres<SR32>(SC, Sst, Sst, 1, 1, g2 + blk * CC, b2 + blk * CC, w, lane);
        __syncthreads();

        if (tid < CC) {
            float v = Sst[tid];
            if (v != v) v = 0.f;
            v = fminf(fmaxf(v, -3.402823466e38f), 3.402823466e38f);
            out[(size_t)g * CC + tid] = v;
        }
    }
}

// ============================================================================
// LONG kernel: genes with len > 32 (rare; persistent over atomic list)
// ============================================================================
__global__ __launch_bounds__(256, 1)
void gene_long64(const float* __restrict__ rf,
                 const float* __restrict__ Wq, const float* __restrict__ Wk,
                 const float* __restrict__ Wv, const float* __restrict__ Wo,
                 const float* __restrict__ bq, const float* __restrict__ bk,
                 const float* __restrict__ bv, const float* __restrict__ bo,
                 const float* __restrict__ Wlin, const float* __restrict__ blin,
                 const float* __restrict__ g1, const float* __restrict__ b1,
                 const float* __restrict__ g2, const float* __restrict__ b2,
                 const float* __restrict__ seed,
                 const int* __restrict__ rxn_idx,
                 float* __restrict__ out)
{
    extern __shared__ float sm[];
    float* Sst = sm;                    // [64][SR64]
    float* SA  = sm + B64;
    float* SB  = SA + B64;              // K^T [128][SKT64] OR normal [64][SR64]
    float* SC  = SB + KT64;
    float* SCR = SC + B64;              // [256]

    int tid  = threadIdx.x;
    int w    = tid >> 5;
    int lane = tid & 31;
    int nlong = g_longcount;

    for (int i = blockIdx.x; i < nlong; i += gridDim.x) {
        int g     = g_longlist[i];
        int start = g_starts[g];
        int cnt   = g_starts[g + 1] - start;
        int len   = cnt < 64 ? cnt : 64;
        int lenr  = (len + 7) & ~7;
        if (lenr > 64) lenr = 64;

        for (int r = w; r < lenr; r += 8) {
            if (r < len) {
                int rx = rxn_idx[start + r];
                ((float4*)(Sst + r * SR64))[lane] = ((const float4*)(rf + (size_t)rx * CC))[lane];
            } else {
                ((float4*)(Sst + r * SR64))[lane] = make_float4(0.f, 0.f, 0.f, 0.f);
            }
        }
        __syncthreads();

        for (int blk = 0; blk < 2; blk++) {
            const float* wq = Wq + blk * CC * CC;  const float* wk = Wk + blk * CC * CC;
            const float* wv = Wv + blk * CC * CC;  const float* wo = Wo + blk * CC * CC;
            const float* wl = Wlin + blk * CC * CC;
            mm64row<false, false>(Sst, wq, bq + blk * CC, SA, lenr, w, lane);
            mm64row<true,  false>(Sst, wk, bk + blk * CC, SB, lenr, w, lane);
            mm64row<false, false>(Sst, wv, bv + blk * CC, SC, lenr, w, lane);
            __syncthreads();
            attn64(SA, SB, SC, lenr, len, lenr, w, lane);
            __syncthreads();
            mm64row<false, false>(SA, wo, bo + blk * CC, SB, lenr, w, lane);
            __syncthreads();
            lnres<SR64>(SB, Sst, Sst, lenr, len, g1 + blk * CC, b1 + blk * CC, w, lane);
            __syncthreads();
            mm64row<false, true>(Sst, wl, blin + blk * CC, SC, lenr, w, lane);
            __syncthreads();
            lnres<SR64>(SC, Sst, Sst, lenr, lenr, g2 + blk * CC, b2 + blk * CC, w, lane);
            __syncthreads();
        }
        {
            const int blk = 2;
            mm1_part(seed, Wq + blk * CC * CC, SCR, tid);
            mm64row<true,  false>(Sst, Wk + blk * CC * CC, bk + blk * CC, SB, lenr, w, lane);
            mm64row<false, false>(Sst, Wv + blk * CC * CC, bv + blk * CC, SC, lenr, w, lane);
            __syncthreads();
            mm1_fin<false>(SCR, bq + blk * CC, SA, tid);
            __syncthreads();
            attn64(SA, SB, SC, 1, len, lenr, w, lane);
            __syncthreads();
            mm1_part(SA, Wo + blk * CC * CC, SCR, tid);
            __syncthreads();
            mm1_fin<false>(SCR, bo + blk * CC, SB, tid);
            __syncthreads();
            lnres<SR64>(SB, seed, Sst, 1, 1, g1 + blk * CC, b1 + blk * CC, w, lane);
            __syncthreads();
            mm1_part(Sst, Wlin + blk * CC * CC, SCR, tid);
            __syncthreads();
            mm1_fin<true>(SCR, blin + blk * CC, SC, tid);
            __syncthreads();
            lnres<SR64>(SC, Sst, Sst, 1, 1, g2 + blk * CC, b2 + blk * CC, w, lane);
            __syncthreads();
        }
        {
            const int blk = 3;
            mm1_part(Sst, Wv + blk * CC * CC, SCR, tid);
            __syncthreads();
            mm1_fin<false>(SCR, bv + blk * CC, SA, tid);
            __syncthreads();
            mm1_part(SA, Wo + blk * CC * CC, SCR, tid);
            __syncthreads();
            mm1_fin<false>(SCR, bo + blk * CC, SB, tid);
            __syncthreads();
            lnres<SR64>(SB, Sst, Sst, 1, 1, g1 + blk * CC, b1 + blk * CC, w, lane);
            __syncthreads();
            mm1_part(Sst, Wlin + blk * CC * CC, SCR, tid);
            __syncthreads();
            mm1_fin<true>(SCR, blin + blk * CC, SC, tid);
            __syncthreads();
            lnres<SR64>(SC, Sst, Sst, 1, 1, g2 + blk * CC, b2 + blk * CC, w, lane);
            __syncthreads();

            if (tid < CC) {
                float v = Sst[tid];
                if (v != v) v = 0.f;
                v = fminf(fmaxf(v, -3.402823466e38f), 3.402823466e38f);
                out[(size_t)g * CC + tid] = v;
            }
        }
        __syncthreads();    // Sst reused next iteration
    }
}

extern "C" void kernel_launch(void* const* d_in, const int* in_sizes, int n_in,
                              void* d_out, int out_size)
{
    const float* rf   = (const float*)d_in[0];
    const float* Wq   = (const float*)d_in[1];
    const float* Wk   = (const float*)d_in[2];
    const float* Wv   = (const float*)d_in[3];
    const float* Wo   = (const float*)d_in[4];
    const float* bq   = (const float*)d_in[5];
    const float* bk   = (const float*)d_in[6];
    const float* bv   = (const float*)d_in[7];
    const float* bo   = (const float*)d_in[8];
    const float* Wlin = (const float*)d_in[9];
    const float* blin = (const float*)d_in[10];
    const float* g1   = (const float*)d_in[11];
    const float* b1   = (const float*)d_in[12];
    const float* g2   = (const float*)d_in[13];
    const float* b2   = (const float*)d_in[14];
    const float* seed = (const float*)d_in[15];
    const int*   rxn  = (const int*)d_in[16];
    const int*   gidx = (const int*)d_in[17];
    int E = in_sizes[16];

    cudaFuncSetAttribute(gene_main32, cudaFuncAttributeMaxDynamicSharedMemorySize, SM32_BYTES);
    cudaFuncSetAttribute(gene_long64, cudaFuncAttributeMaxDynamicSharedMemorySize, SM64_BYTES);

    seg_bounds_kernel<<<(E + 255) / 256, 256>>>(gidx, E);
    gene_main32<<<GENES, 256, SM32_BYTES>>>(rf, Wq, Wk, Wv, Wo, bq, bk, bv, bo,
                                            Wlin, blin, g1, b1, g2, b2, seed, rxn,
                                            (float*)d_out);
    gene_long64<<<128, 256, SM64_BYTES>>>(rf, Wq, Wk, Wv, Wo, bq, bk, bv, bo,
                                          Wlin, blin, g1, b1, g2, b2, seed, rxn,
                                          (float*)d_out);
}

// round 7
// speedup vs baseline: 1.4931x; 1.4931x over previous
#include <cuda_runtime.h>
#include <math.h>

#define CC    128
#define GENES 4096

// ---- main (len<=32) kernel geometry ----
#define SR32  132                 // row stride (floats)
#define SKT32 33                  // K^T stride
#define B32   (32 * SR32)         // 4224 floats
#define KT32  (128 * SKT32)       // 4224 floats
#define SM32_FLOATS (3 * B32 + KT32 + 256)
#define SM32_BYTES  (SM32_FLOATS * 4)      // ~68.6 KB -> 3 CTAs/SM

// ---- long (len>32) kernel geometry ----
#define SR64  136
#define SKT64 69
#define B64   (64 * SR64)
#define KT64  (128 * SKT64)
#define SM64_FLOATS (3 * B64 + KT64 + 256)
#define SM64_BYTES  (SM64_FLOATS * 4)

__device__ int g_starts[GENES + 1];
__device__ int g_longcount;
__device__ int g_longlist[GENES];

__device__ __forceinline__ float warp_sum(float v) {
#pragma unroll
    for (int o = 16; o; o >>= 1) v += __shfl_xor_sync(0xffffffffu, v, o);
    return v;
}
__device__ __forceinline__ float warp_max(float v) {
#pragma unroll
    for (int o = 16; o; o >>= 1) v = fmaxf(v, __shfl_xor_sync(0xffffffffu, v, o));
    return v;
}

// ============================================================================
// bounds kernel: mark segment starts (gene_idx sorted, every gene nonempty)
// ============================================================================
__global__ void seg_bounds_kernel(const int* __restrict__ gene_idx, int E)
{
    int e = blockIdx.x * 256 + threadIdx.x;
    if (e == 0) { g_starts[GENES] = E; g_longcount = 0; }
    if (e < E) {
        int gi = gene_idx[e];
        if (e == 0 || gene_idx[e - 1] != gi) g_starts[gi] = e;
    }
}

// ============================================================================
// mm32s<NS>: X[NS*4 rows,128] @ W + b -> Y.  8 warps = 4 row-groups x 2 halves.
// NS = exact row-slots per warp (lenr/4) -> NO row guards, every FMA useful.
// Warp loads half of W (float2 per lane). X loads are warp-broadcast LDS.
// ============================================================================
template <int NS, bool TRANS, bool RELU>
__device__ __forceinline__ void mm32s(const float* X, const float* __restrict__ W,
                                      const float* __restrict__ bias, float* Y,
                                      int w, int lane)
{
    int rg = w >> 1;                    // 0..3, rows rg, rg+4, ...
    int ch = w & 1;                     // col half
    int c0 = ch * 64 + lane * 2;
    float acc[NS][2];
#pragma unroll
    for (int i = 0; i < NS; i++) { acc[i][0] = 0.f; acc[i][1] = 0.f; }

#pragma unroll 2
    for (int kk = 0; kk < CC; kk += 4) {
        float2 w0 = *(const float2*)(W + (kk + 0) * CC + c0);
        float2 w1 = *(const float2*)(W + (kk + 1) * CC + c0);
        float2 w2 = *(const float2*)(W + (kk + 2) * CC + c0);
        float2 w3 = *(const float2*)(W + (kk + 3) * CC + c0);
#pragma unroll
        for (int i = 0; i < NS; i++) {
            float4 xv = *(const float4*)(X + (rg + 4 * i) * SR32 + kk);
            acc[i][0] = fmaf(xv.x, w0.x, acc[i][0]);
            acc[i][1] = fmaf(xv.x, w0.y, acc[i][1]);
            acc[i][0] = fmaf(xv.y, w1.x, acc[i][0]);
            acc[i][1] = fmaf(xv.y, w1.y, acc[i][1]);
            acc[i][0] = fmaf(xv.z, w2.x, acc[i][0]);
            acc[i][1] = fmaf(xv.z, w2.y, acc[i][1]);
            acc[i][0] = fmaf(xv.w, w3.x, acc[i][0]);
            acc[i][1] = fmaf(xv.w, w3.y, acc[i][1]);
        }
    }
    float2 bv = *(const float2*)(bias + c0);
#pragma unroll
    for (int i = 0; i < NS; i++) {
        int r = rg + 4 * i;
        float o0 = acc[i][0] + bv.x, o1 = acc[i][1] + bv.y;
        if (RELU) { o0 = fmaxf(o0, 0.f); o1 = fmaxf(o1, 0.f); }
        if (!TRANS) {
            *(float2*)(Y + r * SR32 + c0) = make_float2(o0, o1);
        } else {
            Y[(c0 + 0) * SKT32 + r] = o0;
            Y[(c0 + 1) * SKT32 + r] = o1;
        }
    }
}

// ============================================================================
// mm64row: row-split matmul for the long (64-row) kernel (unchanged)
// ============================================================================
template <bool TRANS, bool RELU>
__device__ void mm64row(const float* X, const float* __restrict__ W,
                        const float* __restrict__ bias, float* Y,
                        int rows, int w, int lane)
{
    int nr = (rows > w) ? (((rows - 1 - w) >> 3) + 1) : 0;
    if (nr == 0) return;
    int c0 = lane * 4;
    float acc[8][4];
#pragma unroll
    for (int i = 0; i < 8; i++) { acc[i][0]=0.f; acc[i][1]=0.f; acc[i][2]=0.f; acc[i][3]=0.f; }

#pragma unroll 2
    for (int kk = 0; kk < CC; kk += 4) {
        float4 w0 = *(const float4*)(W + (kk + 0) * CC + c0);
        float4 w1 = *(const float4*)(W + (kk + 1) * CC + c0);
        float4 w2 = *(const float4*)(W + (kk + 2) * CC + c0);
        float4 w3 = *(const float4*)(W + (kk + 3) * CC + c0);
#pragma unroll
        for (int i = 0; i < 8; i++) {
            if (i < nr) {
                float4 xv = *(const float4*)(X + (w + 8 * i) * SR64 + kk);
                acc[i][0]=fmaf(xv.x,w0.x,acc[i][0]); acc[i][1]=fmaf(xv.x,w0.y,acc[i][1]);
                acc[i][2]=fmaf(xv.x,w0.z,acc[i][2]); acc[i][3]=fmaf(xv.x,w0.w,acc[i][3]);
                acc[i][0]=fmaf(xv.y,w1.x,acc[i][0]); acc[i][1]=fmaf(xv.y,w1.y,acc[i][1]);
                acc[i][2]=fmaf(xv.y,w1.z,acc[i][2]); acc[i][3]=fmaf(xv.y,w1.w,acc[i][3]);
                acc[i][0]=fmaf(xv.z,w2.x,acc[i][0]); acc[i][1]=fmaf(xv.z,w2.y,acc[i][1]);
                acc[i][2]=fmaf(xv.z,w2.z,acc[i][2]); acc[i][3]=fmaf(xv.z,w2.w,acc[i][3]);
                acc[i][0]=fmaf(xv.w,w3.x,acc[i][0]); acc[i][1]=fmaf(xv.w,w3.y,acc[i][1]);
                acc[i][2]=fmaf(xv.w,w3.z,acc[i][2]); acc[i][3]=fmaf(xv.w,w3.w,acc[i][3]);
            }
        }
    }
    float4 bv = *(const float4*)(bias + c0);
#pragma unroll
    for (int i = 0; i < 8; i++) {
        if (i < nr) {
            int r = w + 8 * i;
            float o0=acc[i][0]+bv.x, o1=acc[i][1]+bv.y, o2=acc[i][2]+bv.z, o3=acc[i][3]+bv.w;
            if (RELU) { o0=fmaxf(o0,0.f); o1=fmaxf(o1,0.f); o2=fmaxf(o2,0.f); o3=fmaxf(o3,0.f); }
            if (!TRANS) {
                *(float4*)(Y + r * SR64 + c0) = make_float4(o0, o1, o2, o3);
            } else {
                Y[(c0+0)*SKT64 + r]=o0; Y[(c0+1)*SKT64 + r]=o1;
                Y[(c0+2)*SKT64 + r]=o2; Y[(c0+3)*SKT64 + r]=o3;
            }
        }
    }
}

// ============================================================================
// mm1 split over k (2 halves across 256 threads) + finalize
// ============================================================================
__device__ void mm1_part(const float* __restrict__ X, const float* __restrict__ W,
                         float* scratch, int tid)
{
    int col = tid & 127;
    int h   = tid >> 7;                 // 0/1
    const float* Wp = W + (h * 64) * CC + col;
    const float* Xp = X + h * 64;
    float acc = 0.f;
#pragma unroll 8
    for (int k = 0; k < 64; k++) acc = fmaf(Xp[k], Wp[k * CC], acc);
    scratch[tid] = acc;
}
template <bool RELU>
__device__ void mm1_fin(const float* scratch, const float* __restrict__ bias,
                        float* Y, int tid)
{
    if (tid < CC) {
        float v = scratch[tid] + scratch[tid + 128] + bias[tid];
        if (RELU) v = fmaxf(v, 0.f);
        Y[tid] = v;
    }
}

// ============================================================================
// attention, kv rows = KVR (compile-time). One warp per (query row, head).
// lane = kv index for scores; lane = output dim for AV.
// ============================================================================
template <int KVR>
__device__ __forceinline__ void attn32s(float* QO, const float* Kt, const float* V,
                                        int Lq, int len, int w, int lane)
{
    const float scale = 0.17677669529663687f;   // 1/sqrt(32)
    int ntask = Lq * 4;
    for (int t = w; t < ntask; t += 8) {
        int r = t >> 2, base = (t & 3) * 32;
        float s = 0.f;
#pragma unroll
        for (int d = 0; d < 32; d++)
            s = fmaf(QO[r * SR32 + base + d], Kt[(base + d) * SKT32 + lane], s);
        s = (lane < len) ? s * scale : -1e30f;
        float m = warp_max(s);
        float p = __expf(s - m);
        float inv = 1.f / warp_sum(p);
        float a = p * inv;
        float acc = 0.f;
#pragma unroll
        for (int k = 0; k < KVR; k++)
            acc = fmaf(__shfl_sync(0xffffffffu, a, k), V[k * SR32 + base + lane], acc);
        QO[r * SR32 + base + lane] = acc;
    }
}

// attention (kv <= 64) for the long kernel (unchanged)
__device__ void attn64(float* QO, const float* Kt, const float* V,
                       int Lq, int len, int kvr, int w, int lane)
{
    const float scale = 0.17677669529663687f;
    int ntask = Lq * 4;
    for (int t = w; t < ntask; t += 8) {
        int r = t >> 2, base = (t & 3) * 32;
        float s0 = 0.f, s1 = 0.f;
#pragma unroll
        for (int d = 0; d < 32; d++) {
            float qd = QO[r * SR64 + base + d];
            s0 = fmaf(qd, Kt[(base + d) * SKT64 + lane], s0);
            s1 = fmaf(qd, Kt[(base + d) * SKT64 + lane + 32], s1);
        }
        s0 = (lane < len)      ? s0 * scale : -1e30f;
        s1 = (lane + 32 < len) ? s1 * scale : -1e30f;
        float m = warp_max(fmaxf(s0, s1));
        float p0 = __expf(s0 - m), p1 = __expf(s1 - m);
        float inv = 1.f / warp_sum(p0 + p1);
        float a0 = p0 * inv, a1 = p1 * inv;
        float acc = 0.f;
        int k0 = kvr < 32 ? kvr : 32;
        for (int k = 0; k < k0; k++)
            acc = fmaf(__shfl_sync(0xffffffffu, a0, k), V[k * SR64 + base + lane], acc);
        for (int k = 32; k < kvr; k++)
            acc = fmaf(__shfl_sync(0xffffffffu, a1, k - 32), V[k * SR64 + base + lane], acc);
        QO[r * SR64 + base + lane] = acc;
    }
}

// ============================================================================
// LN(residual + masked A) row-wise over 128
// ============================================================================
template <int SROW>
__device__ void lnres(const float* A, const float* Res, float* Out,
                      int rows, int qmasklen,
                      const float* __restrict__ g, const float* __restrict__ b,
                      int w, int lane)
{
    for (int r = w; r < rows; r += 8) {
        float4 a = (r < qmasklen) ? *(const float4*)(A + r * SROW + lane * 4)
                                  : make_float4(0.f, 0.f, 0.f, 0.f);
        float4 s = *(const float4*)(Res + r * SROW + lane * 4);
        float t0 = a.x + s.x, t1 = a.y + s.y, t2 = a.z + s.z, t3 = a.w + s.w;
        float sum = warp_sum(t0 + t1 + t2 + t3);
        float sq  = warp_sum(t0*t0 + t1*t1 + t2*t2 + t3*t3);
        float mean = sum * (1.f / 128.f);
        float var  = sq * (1.f / 128.f) - mean * mean;
        float rstd = rsqrtf(var + 1e-5f);
        float4 gv = *(const float4*)(g + lane * 4);
        float4 bv = *(const float4*)(b + lane * 4);
        float4 o;
        o.x = (t0 - mean) * rstd * gv.x + bv.x;
        o.y = (t1 - mean) * rstd * gv.y + bv.y;
        o.z = (t2 - mean) * rstd * gv.z + bv.z;
        o.w = (t3 - mean) * rstd * gv.w + bv.w;
        *(float4*)(Out + r * SROW + lane * 4) = o;
    }
}

// ============================================================================
// Specialized encoder(x2) + PMA path for lenr = NS*4
// ============================================================================
template <int NS>
__device__ __forceinline__ void enc_pma(
    float* Sst, float* SA, float* SB, float* SC, float* SCR,
    const float* __restrict__ Wq, const float* __restrict__ Wk,
    const float* __restrict__ Wv, const float* __restrict__ Wo,
    const float* __restrict__ bq, const float* __restrict__ bk,
    const float* __restrict__ bv, const float* __restrict__ bo,
    const float* __restrict__ Wlin, const float* __restrict__ blin,
    const float* __restrict__ g1, const float* __restrict__ b1,
    const float* __restrict__ g2, const float* __restrict__ b2,
    const float* __restrict__ seed,
    int len, int w, int lane, int tid)
{
    constexpr int ROWS = NS * 4;

    // encoder SABs
#pragma unroll 1
    for (int blk = 0; blk < 2; blk++) {
        const float* wq = Wq + blk * CC * CC;  const float* wk = Wk + blk * CC * CC;
        const float* wv = Wv + blk * CC * CC;  const float* wo = Wo + blk * CC * CC;
        const float* wl = Wlin + blk * CC * CC;
        mm32s<NS, false, false>(Sst, wq, bq + blk * CC, SA, w, lane);
        mm32s<NS, true,  false>(Sst, wk, bk + blk * CC, SB, w, lane);
        mm32s<NS, false, false>(Sst, wv, bv + blk * CC, SC, w, lane);
        __syncthreads();
        attn32s<ROWS>(SA, SB, SC, ROWS, len, w, lane);
        __syncthreads();
        mm32s<NS, false, false>(SA, wo, bo + blk * CC, SB, w, lane);
        __syncthreads();
        lnres<SR32>(SB, Sst, Sst, ROWS, len, g1 + blk * CC, b1 + blk * CC, w, lane);
        __syncthreads();
        mm32s<NS, false, true>(Sst, wl, blin + blk * CC, SC, w, lane);
        __syncthreads();
        lnres<SR32>(SC, Sst, Sst, ROWS, ROWS, g2 + blk * CC, b2 + blk * CC, w, lane);
        __syncthreads();
    }

    // PMA (block 2)
    {
        const int blk = 2;
        mm1_part(seed, Wq + blk * CC * CC, SCR, tid);
        mm32s<NS, true,  false>(Sst, Wk + blk * CC * CC, bk + blk * CC, SB, w, lane);
        mm32s<NS, false, false>(Sst, Wv + blk * CC * CC, bv + blk * CC, SC, w, lane);
        __syncthreads();
        mm1_fin<false>(SCR, bq + blk * CC, SA, tid);    // Q row0
        __syncthreads();
        attn32s<ROWS>(SA, SB, SC, 1, len, w, lane);
        __syncthreads();
        mm1_part(SA, Wo + blk * CC * CC, SCR, tid);
        __syncthreads();
        mm1_fin<false>(SCR, bo + blk * CC, SB, tid);
        __syncthreads();
        lnres<SR32>(SB, seed, Sst, 1, 1, g1 + blk * CC, b1 + blk * CC, w, lane);
        __syncthreads();
        mm1_part(Sst, Wlin + blk * CC * CC, SCR, tid);
        __syncthreads();
        mm1_fin<true>(SCR, blin + blk * CC, SC, tid);
        __syncthreads();
        lnres<SR32>(SC, Sst, Sst, 1, 1, g2 + blk * CC, b2 + blk * CC, w, lane);
        __syncthreads();
    }
}

// ============================================================================
// MAIN kernel: genes with len <= 32 (3 CTAs/SM)
// ============================================================================
__global__ __launch_bounds__(256, 3)
void gene_main32(const float* __restrict__ rf,
                 const float* __restrict__ Wq, const float* __restrict__ Wk,
                 const float* __restrict__ Wv, const float* __restrict__ Wo,
                 const float* __restrict__ bq, const float* __restrict__ bk,
                 const float* __restrict__ bv, const float* __restrict__ bo,
                 const float* __restrict__ Wlin, const float* __restrict__ blin,
                 const float* __restrict__ g1, const float* __restrict__ b1,
                 const float* __restrict__ g2, const float* __restrict__ b2,
                 const float* __restrict__ seed,
                 const int* __restrict__ rxn_idx,
                 float* __restrict__ out)
{
    extern __shared__ float sm[];
    float* Sst = sm;                    // state        [32][SR32]
    float* SA  = sm + B32;              // Q / attn-O   [32][SR32]
    float* SB  = SA + B32;              // K^T [128][SKT32] OR normal [32][SR32]
    float* SC  = SB + KT32;             // V / FF       [32][SR32]
    float* SCR = SC + B32;              // mm1 scratch  [256]

    int g    = blockIdx.x;
    int tid  = threadIdx.x;
    int w    = tid >> 5;
    int lane = tid & 31;

    int start = g_starts[g];
    int len   = g_starts[g + 1] - start;
    if (len > 32) {                     // defer to long kernel
        if (tid == 0) { int p = atomicAdd(&g_longcount, 1); g_longlist[p] = g; }
        return;
    }
    int lenr = (len + 7) & ~7;          // 8..32

    // gather
    for (int r = w; r < lenr; r += 8) {
        if (r < len) {
            int rx = rxn_idx[start + r];
            ((float4*)(Sst + r * SR32))[lane] = ((const float4*)(rf + (size_t)rx * CC))[lane];
        } else {
            ((float4*)(Sst + r * SR32))[lane] = make_float4(0.f, 0.f, 0.f, 0.f);
        }
    }
    __syncthreads();

    // dispatch on exact padded length -> zero row-guard overhead inside
    switch (lenr) {
    case 8:
        enc_pma<2>(Sst, SA, SB, SC, SCR, Wq, Wk, Wv, Wo, bq, bk, bv, bo,
                   Wlin, blin, g1, b1, g2, b2, seed, len, w, lane, tid);
        break;
    case 16:
        enc_pma<4>(Sst, SA, SB, SC, SCR, Wq, Wk, Wv, Wo, bq, bk, bv, bo,
                   Wlin, blin, g1, b1, g2, b2, seed, len, w, lane, tid);
        break;
    case 24:
        enc_pma<6>(Sst, SA, SB, SC, SCR, Wq, Wk, Wv, Wo, bq, bk, bv, bo,
                   Wlin, blin, g1, b1, g2, b2, seed, len, w, lane, tid);
        break;
    default:
        enc_pma<8>(Sst, SA, SB, SC, SCR, Wq, Wk, Wv, Wo, bq, bk, bv, bo,
                   Wlin, blin, g1, b1, g2, b2, seed, len, w, lane, tid);
        break;
    }

    // decoder SAB (block 3): Lq=Lk=1 -> attn = V
    {
        const int blk = 3;
        mm1_part(Sst, Wv + blk * CC * CC, SCR, tid);
        __syncthreads();
        mm1_fin<false>(SCR, bv + blk * CC, SA, tid);
        __syncthreads();
        mm1_part(SA, Wo + blk * CC * CC, SCR, tid);
        __syncthreads();
        mm1_fin<false>(SCR, bo + blk * CC, SB, tid);
        __syncthreads();
        lnres<SR32>(SB, Sst, Sst, 1, 1, g1 + blk * CC, b1 + blk * CC, w, lane);
        __syncthreads();
        mm1_part(Sst, Wlin + blk * CC * CC, SCR, tid);
        __syncthreads();
        mm1_fin<true>(SCR, blin + blk * CC, SC, tid);
        __syncthreads();
        lnres<SR32>(SC, Sst, Sst, 1, 1, g2 + blk * CC, b2 + blk * CC, w, lane);
        __syncthreads();

        if (tid < CC) {
            float v = Sst[tid];
            if (v != v) v = 0.f;
            v = fminf(fmaxf(v, -3.402823466e38f), 3.402823466e38f);
            out[(size_t)g * CC + tid] = v;
        }
    }
}

// ============================================================================
// LONG kernel: genes with len > 32 (rare; persistent over atomic list)
// ============================================================================
__global__ __launch_bounds__(256, 1)
void gene_long64(const float* __restrict__ rf,
                 const float* __restrict__ Wq, const float* __restrict__ Wk,
                 const float* __restrict__ Wv, const float* __restrict__ Wo,
                 const float* __restrict__ bq, const float* __restrict__ bk,
                 const float* __restrict__ bv, const float* __restrict__ bo,
                 const float* __restrict__ Wlin, const float* __restrict__ blin,
                 const float* __restrict__ g1, const float* __restrict__ b1,
                 const float* __restrict__ g2, const float* __restrict__ b2,
                 const float* __restrict__ seed,
                 const int* __restrict__ rxn_idx,
                 float* __restrict__ out)
{
    extern __shared__ float sm[];
    float* Sst = sm;                    // [64][SR64]
    float* SA  = sm + B64;
    float* SB  = SA + B64;              // K^T [128][SKT64] OR normal [64][SR64]
    float* SC  = SB + KT64;
    float* SCR = SC + B64;              // [256]

    int tid  = threadIdx.x;
    int w    = tid >> 5;
    int lane = tid & 31;
    int nlong = g_longcount;

    for (int i = blockIdx.x; i < nlong; i += gridDim.x) {
        int g     = g_longlist[i];
        int start = g_starts[g];
        int cnt   = g_starts[g + 1] - start;
        int len   = cnt < 64 ? cnt : 64;
        int lenr  = (len + 7) & ~7;
        if (lenr > 64) lenr = 64;

        for (int r = w; r < lenr; r += 8) {
            if (r < len) {
                int rx = rxn_idx[start + r];
                ((float4*)(Sst + r * SR64))[lane] = ((const float4*)(rf + (size_t)rx * CC))[lane];
            } else {
                ((float4*)(Sst + r * SR64))[lane] = make_float4(0.f, 0.f, 0.f, 0.f);
            }
        }
        __syncthreads();

        for (int blk = 0; blk < 2; blk++) {
            const float* wq = Wq + blk * CC * CC;  const float* wk = Wk + blk * CC * CC;
            const float* wv = Wv + blk * CC * CC;  const float* wo = Wo + blk * CC * CC;
            const float* wl = Wlin + blk * CC * CC;
            mm64row<false, false>(Sst, wq, bq + blk * CC, SA, lenr, w, lane);
            mm64row<true,  false>(Sst, wk, bk + blk * CC, SB, lenr, w, lane);
            mm64row<false, false>(Sst, wv, bv + blk * CC, SC, lenr, w, lane);
            __syncthreads();
            attn64(SA, SB, SC, lenr, len, lenr, w, lane);
            __syncthreads();
            mm64row<false, false>(SA, wo, bo + blk * CC, SB, lenr, w, lane);
            __syncthreads();
            lnres<SR64>(SB, Sst, Sst, lenr, len, g1 + blk * CC, b1 + blk * CC, w, lane);
            __syncthreads();
            mm64row<false, true>(Sst, wl, blin + blk * CC, SC, lenr, w, lane);
            __syncthreads();
            lnres<SR64>(SC, Sst, Sst, lenr, lenr, g2 + blk * CC, b2 + blk * CC, w, lane);
            __syncthreads();
        }
        {
            const int blk = 2;
            mm1_part(seed, Wq + blk * CC * CC, SCR, tid);
            mm64row<true,  false>(Sst, Wk + blk * CC * CC, bk + blk * CC, SB, lenr, w, lane);
            mm64row<false, false>(Sst, Wv + blk * CC * CC, bv + blk * CC, SC, lenr, w, lane);
            __syncthreads();
            mm1_fin<false>(SCR, bq + blk * CC, SA, tid);
            __syncthreads();
            attn64(SA, SB, SC, 1, len, lenr, w, lane);
            __syncthreads();
            mm1_part(SA, Wo + blk * CC * CC, SCR, tid);
            __syncthreads();
            mm1_fin<false>(SCR, bo + blk * CC, SB, tid);
            __syncthreads();
            lnres<SR64>(SB, seed, Sst, 1, 1, g1 + blk * CC, b1 + blk * CC, w, lane);
            __syncthreads();
            mm1_part(Sst, Wlin + blk * CC * CC, SCR, tid);
            __syncthreads();
            mm1_fin<true>(SCR, blin + blk * CC, SC, tid);
            __syncthreads();
            lnres<SR64>(SC, Sst, Sst, 1, 1, g2 + blk * CC, b2 + blk * CC, w, lane);
            __syncthreads();
        }
        {
            const int blk = 3;
            mm1_part(Sst, Wv + blk * CC * CC, SCR, tid);
            __syncthreads();
            mm1_fin<false>(SCR, bv + blk * CC, SA, tid);
            __syncthreads();
            mm1_part(SA, Wo + blk * CC * CC, SCR, tid);
            __syncthreads();
            mm1_fin<false>(SCR, bo + blk * CC, SB, tid);
            __syncthreads();
            lnres<SR64>(SB, Sst, Sst, 1, 1, g1 + blk * CC, b1 + blk * CC, w, lane);
            __syncthreads();
            mm1_part(Sst, Wlin + blk * CC * CC, SCR, tid);
            __syncthreads();
            mm1_fin<true>(SCR, blin + blk * CC, SC, tid);
            __syncthreads();
            lnres<SR64>(SC, Sst, Sst, 1, 1, g2 + blk * CC, b2 + blk * CC, w, lane);
            __syncthreads();

            if (tid < CC) {
                float v = Sst[tid];
                if (v != v) v = 0.f;
                v = fminf(fmaxf(v, -3.402823466e38f), 3.402823466e38f);
                out[(size_t)g * CC + tid] = v;
            }
        }
        __syncthreads();    // Sst reused next iteration
    }
}

extern "C" void kernel_launch(void* const* d_in, const int* in_sizes, int n_in,
                              void* d_out, int out_size)
{
    const float* rf   = (const float*)d_in[0];
    const float* Wq   = (const float*)d_in[1];
    const float* Wk   = (const float*)d_in[2];
    const float* Wv   = (const float*)d_in[3];
    const float* Wo   = (const float*)d_in[4];
    const float* bq   = (const float*)d_in[5];
    const float* bk   = (const float*)d_in[6];
    const float* bv   = (const float*)d_in[7];
    const float* bo   = (const float*)d_in[8];
    const float* Wlin = (const float*)d_in[9];
    const float* blin = (const float*)d_in[10];
    const float* g1   = (const float*)d_in[11];
    const float* b1   = (const float*)d_in[12];
    const float* g2   = (const float*)d_in[13];
    const float* b2   = (const float*)d_in[14];
    const float* seed = (const float*)d_in[15];
    const int*   rxn  = (const int*)d_in[16];
    const int*   gidx = (const int*)d_in[17];
    int E = in_sizes[16];

    cudaFuncSetAttribute(gene_main32, cudaFuncAttributeMaxDynamicSharedMemorySize, SM32_BYTES);
    cudaFuncSetAttribute(gene_long64, cudaFuncAttributeMaxDynamicSharedMemorySize, SM64_BYTES);

    seg_bounds_kernel<<<(E + 255) / 256, 256>>>(gidx, E);
    gene_main32<<<GENES, 256, SM32_BYTES>>>(rf, Wq, Wk, Wv, Wo, bq, bk, bv, bo,
                                            Wlin, blin, g1, b1, g2, b2, seed, rxn,
                                            (float*)d_out);
    gene_long64<<<128, 256, SM64_BYTES>>>(rf, Wq, Wk, Wv, Wo, bq, bk, bv, bo,
                                          Wlin, blin, g1, b1, g2, b2, seed, rxn,
                                          (float*)d_out);
}

// round 8
// speedup vs baseline: 1.5837x; 1.0607x over previous
#include <cuda_runtime.h>
#include <math.h>

#define CC    128
#define GENES 4096

// ---- main (len<=32) kernel geometry ----
#define SR32  132                 // row stride (floats)
#define SKT32 33                  // K^T stride
#define B32   (32 * SR32)         // 4224 floats
#define KT32  (128 * SKT32)       // 4224 floats
#define SM32_FLOATS (3 * B32 + KT32)
#define SM32_BYTES  (SM32_FLOATS * 4)      // ~67.6 KB -> 3 CTAs/SM

// ---- long (len>32) kernel geometry ----
#define SR64  136
#define SKT64 69
#define B64   (64 * SR64)
#define KT64  (128 * SKT64)
#define SM64_FLOATS (3 * B64 + KT64)
#define SM64_BYTES  (SM64_FLOATS * 4)

// ---- tail kernel: 3 row-buffers only ----
#define SMT_BYTES (3 * B32 * 4)

__device__ int   g_starts[GENES + 1];
__device__ int   g_longcount;
__device__ int   g_longlist[GENES];
__device__ float g_qpma[CC];              // seed @ Wq[2] + bq[2] (constant)
__device__ float g_pma[GENES * CC];       // PMA attention output per gene

__device__ __forceinline__ float warp_sum(float v) {
#pragma unroll
    for (int o = 16; o; o >>= 1) v += __shfl_xor_sync(0xffffffffu, v, o);
    return v;
}
__device__ __forceinline__ float warp_max(float v) {
#pragma unroll
    for (int o = 16; o; o >>= 1) v = fmaxf(v, __shfl_xor_sync(0xffffffffu, v, o));
    return v;
}

// ============================================================================
// bounds kernel + PMA-Q precompute
// ============================================================================
__global__ void seg_bounds_kernel(const int* __restrict__ gene_idx, int E)
{
    int e = blockIdx.x * 256 + threadIdx.x;
    if (e == 0) { g_starts[GENES] = E; g_longcount = 0; }
    if (e < E) {
        int gi = gene_idx[e];
        if (e == 0 || gene_idx[e - 1] != gi) g_starts[gi] = e;
    }
}

__global__ void prep_qpma_kernel(const float* __restrict__ Wq,
                                 const float* __restrict__ bq,
                                 const float* __restrict__ seed)
{
    int c = threadIdx.x;                       // 128 threads
    float acc = bq[2 * CC + c];
    const float* W2 = Wq + 2 * CC * CC;
#pragma unroll 8
    for (int k = 0; k < CC; k++) acc = fmaf(seed[k], W2[k * CC + c], acc);
    g_qpma[c] = acc;
}

// ============================================================================
// mm32s<NS>: X[NS*4 rows,128] @ W + b -> Y.  8 warps = 4 row-groups x 2 halves.
// NS = exact row-slots per warp -> no row guards. float2 W loads per lane.
// ============================================================================
template <int NS, bool TRANS, bool RELU>
__device__ __forceinline__ void mm32s(const float* X, const float* __restrict__ W,
                                      const float* __restrict__ bias, float* Y,
                                      int w, int lane)
{
    int rg = w >> 1;                    // 0..3, rows rg, rg+4, ...
    int ch = w & 1;                     // col half
    int c0 = ch * 64 + lane * 2;
    float acc[NS][2];
#pragma unroll
    for (int i = 0; i < NS; i++) { acc[i][0] = 0.f; acc[i][1] = 0.f; }

#pragma unroll 2
    for (int kk = 0; kk < CC; kk += 4) {
        float2 w0 = *(const float2*)(W + (kk + 0) * CC + c0);
        float2 w1 = *(const float2*)(W + (kk + 1) * CC + c0);
        float2 w2 = *(const float2*)(W + (kk + 2) * CC + c0);
        float2 w3 = *(const float2*)(W + (kk + 3) * CC + c0);
#pragma unroll
        for (int i = 0; i < NS; i++) {
            float4 xv = *(const float4*)(X + (rg + 4 * i) * SR32 + kk);
            acc[i][0] = fmaf(xv.x, w0.x, acc[i][0]);
            acc[i][1] = fmaf(xv.x, w0.y, acc[i][1]);
            acc[i][0] = fmaf(xv.y, w1.x, acc[i][0]);
            acc[i][1] = fmaf(xv.y, w1.y, acc[i][1]);
            acc[i][0] = fmaf(xv.z, w2.x, acc[i][0]);
            acc[i][1] = fmaf(xv.z, w2.y, acc[i][1]);
            acc[i][0] = fmaf(xv.w, w3.x, acc[i][0]);
            acc[i][1] = fmaf(xv.w, w3.y, acc[i][1]);
        }
    }
    float2 bv = *(const float2*)(bias + c0);
#pragma unroll
    for (int i = 0; i < NS; i++) {
        int r = rg + 4 * i;
        float o0 = acc[i][0] + bv.x, o1 = acc[i][1] + bv.y;
        if (RELU) { o0 = fmaxf(o0, 0.f); o1 = fmaxf(o1, 0.f); }
        if (!TRANS) {
            *(float2*)(Y + r * SR32 + c0) = make_float2(o0, o1);
        } else {
            Y[(c0 + 0) * SKT32 + r] = o0;
            Y[(c0 + 1) * SKT32 + r] = o1;
        }
    }
}

// ============================================================================
// mm64row: row-split matmul for the long (64-row) kernel
// ============================================================================
template <bool TRANS, bool RELU>
__device__ void mm64row(const float* X, const float* __restrict__ W,
                        const float* __restrict__ bias, float* Y,
                        int rows, int w, int lane)
{
    int nr = (rows > w) ? (((rows - 1 - w) >> 3) + 1) : 0;
    if (nr == 0) return;
    int c0 = lane * 4;
    float acc[8][4];
#pragma unroll
    for (int i = 0; i < 8; i++) { acc[i][0]=0.f; acc[i][1]=0.f; acc[i][2]=0.f; acc[i][3]=0.f; }

#pragma unroll 2
    for (int kk = 0; kk < CC; kk += 4) {
        float4 w0 = *(const float4*)(W + (kk + 0) * CC + c0);
        float4 w1 = *(const float4*)(W + (kk + 1) * CC + c0);
        float4 w2 = *(const float4*)(W + (kk + 2) * CC + c0);
        float4 w3 = *(const float4*)(W + (kk + 3) * CC + c0);
#pragma unroll
        for (int i = 0; i < 8; i++) {
            if (i < nr) {
                float4 xv = *(const float4*)(X + (w + 8 * i) * SR64 + kk);
                acc[i][0]=fmaf(xv.x,w0.x,acc[i][0]); acc[i][1]=fmaf(xv.x,w0.y,acc[i][1]);
                acc[i][2]=fmaf(xv.x,w0.z,acc[i][2]); acc[i][3]=fmaf(xv.x,w0.w,acc[i][3]);
                acc[i][0]=fmaf(xv.y,w1.x,acc[i][0]); acc[i][1]=fmaf(xv.y,w1.y,acc[i][1]);
                acc[i][2]=fmaf(xv.y,w1.z,acc[i][2]); acc[i][3]=fmaf(xv.y,w1.w,acc[i][3]);
                acc[i][0]=fmaf(xv.z,w2.x,acc[i][0]); acc[i][1]=fmaf(xv.z,w2.y,acc[i][1]);
                acc[i][2]=fmaf(xv.z,w2.z,acc[i][2]); acc[i][3]=fmaf(xv.z,w2.w,acc[i][3]);
                acc[i][0]=fmaf(xv.w,w3.x,acc[i][0]); acc[i][1]=fmaf(xv.w,w3.y,acc[i][1]);
                acc[i][2]=fmaf(xv.w,w3.z,acc[i][2]); acc[i][3]=fmaf(xv.w,w3.w,acc[i][3]);
            }
        }
    }
    float4 bv = *(const float4*)(bias + c0);
#pragma unroll
    for (int i = 0; i < 8; i++) {
        if (i < nr) {
            int r = w + 8 * i;
            float o0=acc[i][0]+bv.x, o1=acc[i][1]+bv.y, o2=acc[i][2]+bv.z, o3=acc[i][3]+bv.w;
            if (RELU) { o0=fmaxf(o0,0.f); o1=fmaxf(o1,0.f); o2=fmaxf(o2,0.f); o3=fmaxf(o3,0.f); }
            if (!TRANS) {
                *(float4*)(Y + r * SR64 + c0) = make_float4(o0, o1, o2, o3);
            } else {
                Y[(c0+0)*SKT64 + r]=o0; Y[(c0+1)*SKT64 + r]=o1;
                Y[(c0+2)*SKT64 + r]=o2; Y[(c0+3)*SKT64 + r]=o3;
            }
        }
    }
}

// ============================================================================
// attention, kv rows = KVR (compile-time). One warp per (query row, head).
// Writes result to outp[r*outStride + base + lane] (may alias Q: disjoint slices).
// ============================================================================
template <int KVR>
__device__ __forceinline__ void attn32s(const float* Q, const float* Kt, const float* V,
                                        float* outp, int outStride,
                                        int Lq, int len, int w, int lane)
{
    const float scale = 0.17677669529663687f;   // 1/sqrt(32)
    int ntask = Lq * 4;
    for (int t = w; t < ntask; t += 8) {
        int r = t >> 2, base = (t & 3) * 32;
        float s = 0.f;
#pragma unroll
        for (int d = 0; d < 32; d++)
            s = fmaf(Q[r * SR32 + base + d], Kt[(base + d) * SKT32 + lane], s);
        s = (lane < len) ? s * scale : -1e30f;
        float m = warp_max(s);
        float p = __expf(s - m);
        float inv = 1.f / warp_sum(p);
        float a = p * inv;
        float acc = 0.f;
#pragma unroll
        for (int k = 0; k < KVR; k++)
            acc = fmaf(__shfl_sync(0xffffffffu, a, k), V[k * SR32 + base + lane], acc);
        outp[r * outStride + base + lane] = acc;
    }
}

// attention (kv <= 64) for the long kernel
__device__ void attn64(const float* Q, const float* Kt, const float* V,
                       float* outp, int outStride,
                       int Lq, int len, int kvr, int w, int lane)
{
    const float scale = 0.17677669529663687f;
    int ntask = Lq * 4;
    for (int t = w; t < ntask; t += 8) {
        int r = t >> 2, base = (t & 3) * 32;
        float s0 = 0.f, s1 = 0.f;
#pragma unroll
        for (int d = 0; d < 32; d++) {
            float qd = Q[r * SR64 + base + d];
            s0 = fmaf(qd, Kt[(base + d) * SKT64 + lane], s0);
            s1 = fmaf(qd, Kt[(base + d) * SKT64 + lane + 32], s1);
        }
        s0 = (lane < len)      ? s0 * scale : -1e30f;
        s1 = (lane + 32 < len) ? s1 * scale : -1e30f;
        float m = warp_max(fmaxf(s0, s1));
        float p0 = __expf(s0 - m), p1 = __expf(s1 - m);
        float inv = 1.f / warp_sum(p0 + p1);
        float a0 = p0 * inv, a1 = p1 * inv;
        float acc = 0.f;
        int k0 = kvr < 32 ? kvr : 32;
        for (int k = 0; k < k0; k++)
            acc = fmaf(__shfl_sync(0xffffffffu, a0, k), V[k * SR64 + base + lane], acc);
        for (int k = 32; k < kvr; k++)
            acc = fmaf(__shfl_sync(0xffffffffu, a1, k - 32), V[k * SR64 + base + lane], acc);
        outp[r * outStride + base + lane] = acc;
    }
}

// ============================================================================
// LN(residual + masked A) row-wise over 128. resStride==0 -> broadcast residual.
// ============================================================================
template <int SROW>
__device__ void lnres(const float* A, const float* Res, int resStride, float* Out,
                      int rows, int qmasklen,
                      const float* __restrict__ g, const float* __restrict__ b,
                      int w, int lane)
{
    for (int r = w; r < rows; r += 8) {
        float4 a = (r < qmasklen) ? *(const float4*)(A + r * SROW + lane * 4)
                                  : make_float4(0.f, 0.f, 0.f, 0.f);
        float4 s = *(const float4*)(Res + r * resStride + lane * 4);
        float t0 = a.x + s.x, t1 = a.y + s.y, t2 = a.z + s.z, t3 = a.w + s.w;
        float sum = warp_sum(t0 + t1 + t2 + t3);
        float sq  = warp_sum(t0*t0 + t1*t1 + t2*t2 + t3*t3);
        float mean = sum * (1.f / 128.f);
        float var  = sq * (1.f / 128.f) - mean * mean;
        float rstd = rsqrtf(var + 1e-5f);
        float4 gv = *(const float4*)(g + lane * 4);
        float4 bv = *(const float4*)(b + lane * 4);
        float4 o;
        o.x = (t0 - mean) * rstd * gv.x + bv.x;
        o.y = (t1 - mean) * rstd * gv.y + bv.y;
        o.z = (t2 - mean) * rstd * gv.z + bv.z;
        o.w = (t3 - mean) * rstd * gv.w + bv.w;
        *(float4*)(Out + r * SROW + lane * 4) = o;
    }
}

// ============================================================================
// Specialized encoder(x2) + PMA-attention path for lenr = NS*4
// ============================================================================
template <int NS>
__device__ __forceinline__ void enc_pma(
    float* Sst, float* SA, float* SB, float* SC,
    const float* __restrict__ Wq, const float* __restrict__ Wk,
    const float* __restrict__ Wv, const float* __restrict__ Wo,
    const float* __restrict__ bq, const float* __restrict__ bk,
    const float* __restrict__ bv, const float* __restrict__ bo,
    const float* __restrict__ Wlin, const float* __restrict__ blin,
    const float* __restrict__ g1, const float* __restrict__ b1,
    const float* __restrict__ g2, const float* __restrict__ b2,
    float* pma_out,
    int len, int w, int lane, int tid)
{
    constexpr int ROWS = NS * 4;

    // encoder SABs
#pragma unroll 1
    for (int blk = 0; blk < 2; blk++) {
        const float* wq = Wq + blk * CC * CC;  const float* wk = Wk + blk * CC * CC;
        const float* wv = Wv + blk * CC * CC;  const float* wo = Wo + blk * CC * CC;
        const float* wl = Wlin + blk * CC * CC;
        mm32s<NS, false, false>(Sst, wq, bq + blk * CC, SA, w, lane);
        mm32s<NS, true,  false>(Sst, wk, bk + blk * CC, SB, w, lane);
        mm32s<NS, false, false>(Sst, wv, bv + blk * CC, SC, w, lane);
        __syncthreads();
        attn32s<ROWS>(SA, SB, SC, SA, SR32, ROWS, len, w, lane);
        __syncthreads();
        mm32s<NS, false, false>(SA, wo, bo + blk * CC, SB, w, lane);
        __syncthreads();
        lnres<SR32>(SB, Sst, SR32, Sst, ROWS, len, g1 + blk * CC, b1 + blk * CC, w, lane);
        __syncthreads();
        mm32s<NS, false, true>(Sst, wl, blin + blk * CC, SC, w, lane);
        __syncthreads();
        lnres<SR32>(SC, Sst, SR32, Sst, ROWS, ROWS, g2 + blk * CC, b2 + blk * CC, w, lane);
        __syncthreads();
    }

    // PMA attention (block 2): Q is the precomputed constant vector
    if (tid < CC) SA[tid] = g_qpma[tid];
    mm32s<NS, true,  false>(Sst, Wk + 2 * CC * CC, bk + 2 * CC, SB, w, lane);
    mm32s<NS, false, false>(Sst, Wv + 2 * CC * CC, bv + 2 * CC, SC, w, lane);
    __syncthreads();
    attn32s<ROWS>(SA, SB, SC, pma_out, CC, 1, len, w, lane);
}

// ============================================================================
// MAIN kernel: genes with len <= 32 (3 CTAs/SM); ends after PMA attention
// ============================================================================
__global__ __launch_bounds__(256, 3)
void gene_main32(const float* __restrict__ rf,
                 const float* __restrict__ Wq, const float* __restrict__ Wk,
                 const float* __restrict__ Wv, const float* __restrict__ Wo,
                 const float* __restrict__ bq, const float* __restrict__ bk,
                 const float* __restrict__ bv, const float* __restrict__ bo,
                 const float* __restrict__ Wlin, const float* __restrict__ blin,
                 const float* __restrict__ g1, const float* __restrict__ b1,
                 const float* __restrict__ g2, const float* __restrict__ b2,
                 const int* __restrict__ rxn_idx)
{
    extern __shared__ float sm[];
    float* Sst = sm;                    // state        [32][SR32]
    float* SA  = sm + B32;              // Q / attn-O   [32][SR32]
    float* SB  = SA + B32;              // K^T [128][SKT32] OR normal [32][SR32]
    float* SC  = SB + KT32;             // V / FF       [32][SR32]

    int g    = blockIdx.x;
    int tid  = threadIdx.x;
    int w    = tid >> 5;
    int lane = tid & 31;

    int start = g_starts[g];
    int len   = g_starts[g + 1] - start;
    if (len > 32) {                     // defer to long kernel
        if (tid == 0) { int p = atomicAdd(&g_longcount, 1); g_longlist[p] = g; }
        return;
    }
    int lenr = (len + 7) & ~7;          // 8..32

    // gather
    for (int r = w; r < lenr; r += 8) {
        if (r < len) {
            int rx = rxn_idx[start + r];
            ((float4*)(Sst + r * SR32))[lane] = ((const float4*)(rf + (size_t)rx * CC))[lane];
        } else {
            ((float4*)(Sst + r * SR32))[lane] = make_float4(0.f, 0.f, 0.f, 0.f);
        }
    }
    __syncthreads();

    float* pma_out = g_pma + (size_t)g * CC;
    switch (lenr) {
    case 8:
        enc_pma<2>(Sst, SA, SB, SC, Wq, Wk, Wv, Wo, bq, bk, bv, bo,
                   Wlin, blin, g1, b1, g2, b2, pma_out, len, w, lane, tid);
        break;
    case 16:
        enc_pma<4>(Sst, SA, SB, SC, Wq, Wk, Wv, Wo, bq, bk, bv, bo,
                   Wlin, blin, g1, b1, g2, b2, pma_out, len, w, lane, tid);
        break;
    case 24:
        enc_pma<6>(Sst, SA, SB, SC, Wq, Wk, Wv, Wo, bq, bk, bv, bo,
                   Wlin, blin, g1, b1, g2, b2, pma_out, len, w, lane, tid);
        break;
    default:
        enc_pma<8>(Sst, SA, SB, SC, Wq, Wk, Wv, Wo, bq, bk, bv, bo,
                   Wlin, blin, g1, b1, g2, b2, pma_out, len, w, lane, tid);
        break;
    }
}

// ============================================================================
// LONG kernel: genes with len > 32 (rare); ends after PMA attention
// ============================================================================
__global__ __launch_bounds__(256, 1)
void gene_long64(const float* __restrict__ rf,
                 const float* __restrict__ Wq, const float* __restrict__ Wk,
                 const float* __restrict__ Wv, const float* __restrict__ Wo,
                 const float* __restrict__ bq, const float* __restrict__ bk,
                 const float* __restrict__ bv, const float* __restrict__ bo,
                 const float* __restrict__ Wlin, const float* __restrict__ blin,
                 const float* __restrict__ g1, const float* __restrict__ b1,
                 const float* __restrict__ g2, const float* __restrict__ b2,
                 const int* __restrict__ rxn_idx)
{
    extern __shared__ float sm[];
    float* Sst = sm;                    // [64][SR64]
    float* SA  = sm + B64;
    float* SB  = SA + B64;              // K^T [128][SKT64] OR normal [64][SR64]
    float* SC  = SB + KT64;

    int tid  = threadIdx.x;
    int w    = tid >> 5;
    int lane = tid & 31;
    int nlong = g_longcount;

    for (int i = blockIdx.x; i < nlong; i += gridDim.x) {
        int g     = g_longlist[i];
        int start = g_starts[g];
        int cnt   = g_starts[g + 1] - start;
        int len   = cnt < 64 ? cnt : 64;
        int lenr  = (len + 7) & ~7;
        if (lenr > 64) lenr = 64;

        for (int r = w; r < lenr; r += 8) {
            if (r < len) {
                int rx = rxn_idx[start + r];
                ((float4*)(Sst + r * SR64))[lane] = ((const float4*)(rf + (size_t)rx * CC))[lane];
            } else {
                ((float4*)(Sst + r * SR64))[lane] = make_float4(0.f, 0.f, 0.f, 0.f);
            }
        }
        __syncthreads();

        for (int blk = 0; blk < 2; blk++) {
            const float* wq = Wq + blk * CC * CC;  const float* wk = Wk + blk * CC * CC;
            const float* wv = Wv + blk * CC * CC;  const float* wo = Wo + blk * CC * CC;
            const float* wl = Wlin + blk * CC * CC;
            mm64row<false, false>(Sst, wq, bq + blk * CC, SA, lenr, w, lane);
            mm64row<true,  false>(Sst, wk, bk + blk * CC, SB, lenr, w, lane);
            mm64row<false, false>(Sst, wv, bv + blk * CC, SC, lenr, w, lane);
            __syncthreads();
            attn64(SA, SB, SC, SA, SR64, lenr, len, lenr, w, lane);
            __syncthreads();
            mm64row<false, false>(SA, wo, bo + blk * CC, SB, lenr, w, lane);
            __syncthreads();
            lnres<SR64>(SB, Sst, SR64, Sst, lenr, len, g1 + blk * CC, b1 + blk * CC, w, lane);
            __syncthreads();
            mm64row<false, true>(Sst, wl, blin + blk * CC, SC, lenr, w, lane);
            __syncthreads();
            lnres<SR64>(SC, Sst, SR64, Sst, lenr, lenr, g2 + blk * CC, b2 + blk * CC, w, lane);
            __syncthreads();
        }
        // PMA attention
        if (tid < CC) SA[tid] = g_qpma[tid];
        mm64row<true,  false>(Sst, Wk + 2 * CC * CC, bk + 2 * CC, SB, lenr, w, lane);
        mm64row<false, false>(Sst, Wv + 2 * CC * CC, bv + 2 * CC, SC, lenr, w, lane);
        __syncthreads();
        attn64(SA, SB, SC, g_pma + (size_t)g * CC, CC, 1, len, lenr, w, lane);
        __syncthreads();    // buffers reused next iteration
    }
}

// ============================================================================
// TAIL kernel: batched PMA-projection + decoder over 32 genes per CTA
// ============================================================================
__global__ __launch_bounds__(256)
void gene_tail(const float* __restrict__ Wv, const float* __restrict__ Wo,
               const float* __restrict__ bv, const float* __restrict__ bo,
               const float* __restrict__ Wlin, const float* __restrict__ blin,
               const float* __restrict__ g1, const float* __restrict__ b1,
               const float* __restrict__ g2, const float* __restrict__ b2,
               const float* __restrict__ seed,
               float* __restrict__ out)
{
    extern __shared__ float sm[];
    float* Sst = sm;                    // state [32][SR32]
    float* SA  = sm + B32;
    float* SC  = SA + B32;

    int g0   = blockIdx.x * 32;
    int tid  = threadIdx.x;
    int w    = tid >> 5;
    int lane = tid & 31;

    // load 32 PMA attention vectors
    for (int r = w; r < 32; r += 8)
        ((float4*)(Sst + r * SR32))[lane] = ((const float4*)(g_pma + (size_t)(g0 + r) * CC))[lane];
    __syncthreads();

    // ---- PMA projection + LN/FF (block 2); residual = seed (broadcast) ----
    mm32s<8, false, false>(Sst, Wo + 2 * CC * CC, bo + 2 * CC, SA, w, lane);
    __syncthreads();
    lnres<SR32>(SA, seed, 0, Sst, 32, 32, g1 + 2 * CC, b1 + 2 * CC, w, lane);
    __syncthreads();
    mm32s<8, false, true>(Sst, Wlin + 2 * CC * CC, blin + 2 * CC, SC, w, lane);
    __syncthreads();
    lnres<SR32>(SC, Sst, SR32, Sst, 32, 32, g2 + 2 * CC, b2 + 2 * CC, w, lane);
    __syncthreads();

    // ---- decoder SAB (block 3): Lq=Lk=1 -> attn = V ----
    mm32s<8, false, false>(Sst, Wv + 3 * CC * CC, bv + 3 * CC, SA, w, lane);
    __syncthreads();
    mm32s<8, false, false>(SA, Wo + 3 * CC * CC, bo + 3 * CC, SC, w, lane);
    __syncthreads();
    lnres<SR32>(SC, Sst, SR32, Sst, 32, 32, g1 + 3 * CC, b1 + 3 * CC, w, lane);
    __syncthreads();
    mm32s<8, false, true>(Sst, Wlin + 3 * CC * CC, blin + 3 * CC, SC, w, lane);
    __syncthreads();
    lnres<SR32>(SC, Sst, SR32, Sst, 32, 32, g2 + 3 * CC, b2 + 3 * CC, w, lane);
    __syncthreads();

    // write out with nan_to_num
    for (int r = w; r < 32; r += 8) {
        float4 v = ((const float4*)(Sst + r * SR32))[lane];
        float o[4] = {v.x, v.y, v.z, v.w};
#pragma unroll
        for (int j = 0; j < 4; j++) {
            float x = o[j];
            if (x != x) x = 0.f;
            x = fminf(fmaxf(x, -3.402823466e38f), 3.402823466e38f);
            o[j] = x;
        }
        ((float4*)(out + (size_t)(g0 + r) * CC))[lane] = make_float4(o[0], o[1], o[2], o[3]);
    }
}

extern "C" void kernel_launch(void* const* d_in, const int* in_sizes, int n_in,
                              void* d_out, int out_size)
{
    const float* rf   = (const float*)d_in[0];
    const float* Wq   = (const float*)d_in[1];
    const float* Wk   = (const float*)d_in[2];
    const float* Wv   = (const float*)d_in[3];
    const float* Wo   = (const float*)d_in[4];
    const float* bq   = (const float*)d_in[5];
    const float* bk   = (const float*)d_in[6];
    const float* bv   = (const float*)d_in[7];
    const float* bo   = (const float*)d_in[8];
    const float* Wlin = (const float*)d_in[9];
    const float* blin = (const float*)d_in[10];
    const float* g1   = (const float*)d_in[11];
    const float* b1   = (const float*)d_in[12];
    const float* g2   = (const float*)d_in[13];
    const float* b2   = (const float*)d_in[14];
    const float* seed = (const float*)d_in[15];
    const int*   rxn  = (const int*)d_in[16];
    const int*   gidx = (const int*)d_in[17];
    int E = in_sizes[16];

    cudaFuncSetAttribute(gene_main32, cudaFuncAttributeMaxDynamicSharedMemorySize, SM32_BYTES);
    cudaFuncSetAttribute(gene_long64, cudaFuncAttributeMaxDynamicSharedMemorySize, SM64_BYTES);
    cudaFuncSetAttribute(gene_tail,   cudaFuncAttributeMaxDynamicSharedMemorySize, SMT_BYTES);

    seg_bounds_kernel<<<(E + 255) / 256, 256>>>(gidx, E);
    prep_qpma_kernel<<<1, 128>>>(Wq, bq, seed);
    gene_main32<<<GENES, 256, SM32_BYTES>>>(rf, Wq, Wk, Wv, Wo, bq, bk, bv, bo,
                                            Wlin, blin, g1, b1, g2, b2, rxn);
    gene_long64<<<128, 256, SM64_BYTES>>>(rf, Wq, Wk, Wv, Wo, bq, bk, bv, bo,
                                          Wlin, blin, g1, b1, g2, b2, rxn);
    gene_tail<<<GENES / 32, 256, SMT_BYTES>>>(Wv, Wo, bv, bo, Wlin, blin,
                                              g1, b1, g2, b2, seed, (float*)d_out);
}